// round 15
// baseline (speedup 1.0000x reference)
#include <cuda_runtime.h>
#include <cuda_bf16.h>

#define NN 50000
#define EE 800000
#define HH 128
#define GG 64
#define CC 10
#define CAP 64                      // bucket capacity per node (max degree ~40)
#define BNINV 0.9999950000374997f   // 1/sqrt(1+1e-5)

// ---------------- scratch (device globals; no allocations) ----------------
__device__ float d_tmp[NN * HH];          // h @ W  (fp32)
__device__ float d_agg[NN * HH];          // residual h @ R (fp32)
__device__ float d_h[NN * HH];            // final layer activations (for pool)
__device__ __nv_bfloat16 d_ahi[NN * HH];  // activation hi (bf16)
__device__ __nv_bfloat16 d_alo[NN * HH];  // activation lo (bf16)
__device__ float d_dinv[NN];
__device__ int   d_cursor[NN];            // degree counters / bucket cursors
__device__ int   d_csr_src[NN * CAP];     // bucketed incoming-edge sources
__device__ int   d_pool[GG * HH];
__device__ __nv_bfloat16 d_wt[7 * 2 * HH * HH];  // 7 mats, [hi|lo], transposed [n][k]

// ---------------- setup kernels ----------------
__global__ void zero_kernel() {
    int i = blockIdx.x * blockDim.x + threadIdx.x;
    if (i < NN) d_cursor[i] = 0;
    if (i < GG * HH) d_pool[i] = 0;
}
__global__ void fill_kernel(const int* __restrict__ src, const int* __restrict__ dst) {
    int e = blockIdx.x * blockDim.x + threadIdx.x;
    if (e < EE) {
        int s = src[e], d = dst[e];
        int pos = atomicAdd(&d_cursor[d], 1);
        if (pos < CAP) d_csr_src[d * CAP + pos] = s;
    }
}
__global__ void dinv_kernel() {
    int i = blockIdx.x * blockDim.x + threadIdx.x;
    if (i < NN) d_dinv[i] = rsqrtf((float)min(d_cursor[i], CAP) + 1.0f);
}
__global__ void convert_w(const float* __restrict__ W0, const float* __restrict__ Wh,
                          const float* __restrict__ Rh) {
    int idx = blockIdx.x * blockDim.x + threadIdx.x;
    if (idx >= 7 * HH * HH) return;
    int j = idx >> 14, r = idx & 16383;
    int k = r >> 7, n = r & 127;
    const float* src = (j == 0) ? W0 : (j < 4 ? Wh + (j - 1) * HH * HH : Rh + (j - 4) * HH * HH);
    float v = src[k * HH + n];
    __nv_bfloat16 hi = __float2bfloat16_rn(v);
    d_wt[j * 32768 + n * HH + k]         = hi;   // transposed [n][k]
    d_wt[j * 32768 + 16384 + n * HH + k] = __float2bfloat16_rn(v - __bfloat162float(hi));
}

// ---------------- MMA helpers (plain PTX, valid on base sm_103) ----------------
__device__ __forceinline__ void ldsm4(unsigned* r, unsigned addr) {
    asm volatile("ldmatrix.sync.aligned.m8n8.x4.shared.b16 {%0,%1,%2,%3}, [%4];"
        : "=r"(r[0]), "=r"(r[1]), "=r"(r[2]), "=r"(r[3]) : "r"(addr));
}
__device__ __forceinline__ void mma_bf16(float* c, const unsigned* a, const unsigned* b) {
    asm volatile("mma.sync.aligned.m16n8k16.row.col.f32.bf16.bf16.f32 "
        "{%0,%1,%2,%3}, {%4,%5,%6,%7}, {%8,%9}, {%0,%1,%2,%3};"
        : "+f"(c[0]), "+f"(c[1]), "+f"(c[2]), "+f"(c[3])
        : "r"(a[0]), "r"(a[1]), "r"(a[2]), "r"(a[3]), "r"(b[0]), "r"(b[1]));
}
__device__ __forceinline__ unsigned smem_u32(const void* p) {
    unsigned a;
    asm("{ .reg .u64 t; cvta.to.shared.u64 t, %1; cvt.u32.u64 %0, t; }" : "=r"(a) : "l"(p));
    return a;
}

// ---------------- bf16 split GEMM (512 threads, 16 warps, 8x2 warp grid) ----------------
#define LDA 136
#define ARR (128 * LDA)                 // halves per array
#define GEMM_NT 512

__device__ __forceinline__ void load_arr(const __nv_bfloat16* __restrict__ g,
                                         __nv_bfloat16* s, int row0, int valid) {
    #pragma unroll
    for (int i = threadIdx.x; i < 2048; i += GEMM_NT) {
        int row = i >> 4, col = (i & 15) << 3;
        uint4 v = make_uint4(0u, 0u, 0u, 0u);
        if (row0 + row < valid) v = *(const uint4*)(g + (size_t)(row0 + row) * HH + col);
        *(uint4*)(s + row * LDA + col) = v;
    }
}
// cp.async one K-quarter (32 cols = 4 x 16B per row) of one array
__device__ __forceinline__ void cpa_q(unsigned sdst, const __nv_bfloat16* __restrict__ g,
                                      int row0, int valid, int kq) {
    #pragma unroll
    for (int i = threadIdx.x; i < 512; i += GEMM_NT) {
        int row = i >> 2;
        int col = kq * 32 + ((i & 3) << 3);
        int gr = row0 + row;
        int sz = (gr < valid) ? 16 : 0;
        if (gr >= valid) gr = 0;   // keep address in-bounds (unused when sz=0)
        unsigned sa = sdst + (unsigned)((row * LDA + col) * 2);
        asm volatile("cp.async.cg.shared.global [%0], [%1], 16, %2;"
            :: "r"(sa), "l"(g + (size_t)gr * HH + col), "r"(sz) : "memory");
    }
}
__device__ __forceinline__ void load_split(const float* __restrict__ g,
                                           __nv_bfloat16* shi, __nv_bfloat16* slo,
                                           int row0, int valid) {
    #pragma unroll
    for (int i = threadIdx.x; i < 4096; i += GEMM_NT) {
        int row = i >> 5, col = (i & 31) << 2;
        float4 v = make_float4(0.f, 0.f, 0.f, 0.f);
        if (row0 + row < valid) v = *(const float4*)(g + (size_t)(row0 + row) * HH + col);
        __nv_bfloat16 hx = __float2bfloat16_rn(v.x), hy = __float2bfloat16_rn(v.y);
        __nv_bfloat16 hz = __float2bfloat16_rn(v.z), hw = __float2bfloat16_rn(v.w);
        __nv_bfloat162 h01; h01.x = hx; h01.y = hy;
        __nv_bfloat162 h23; h23.x = hz; h23.y = hw;
        *(__nv_bfloat162*)(shi + row * LDA + col)     = h01;
        *(__nv_bfloat162*)(shi + row * LDA + col + 2) = h23;
        __nv_bfloat162 l01, l23;
        l01.x = __float2bfloat16_rn(v.x - __bfloat162float(hx));
        l01.y = __float2bfloat16_rn(v.y - __bfloat162float(hy));
        l23.x = __float2bfloat16_rn(v.z - __bfloat162float(hz));
        l23.y = __float2bfloat16_rn(v.w - __bfloat162float(hw));
        *(__nv_bfloat162*)(slo + row * LDA + col)     = l01;
        *(__nv_bfloat162*)(slo + row * LDA + col + 2) = l23;
    }
}

template <int NM, bool XF32>
__global__ __launch_bounds__(GEMM_NT, 1) void gemm_tpl(
    const float* __restrict__ Xf,
    const __nv_bfloat16* __restrict__ Ahi, const __nv_bfloat16* __restrict__ Alo,
    const __nv_bfloat16* __restrict__ B1,  const __nv_bfloat16* __restrict__ B2,
    float* __restrict__ out1, float* __restrict__ out2)
{
    extern __shared__ __nv_bfloat16 sm[];
    unsigned base = smem_u32(sm);
    int tid = threadIdx.x, lane = tid & 31, wid = tid >> 5;
    int row0 = blockIdx.x * 128;

    if (XF32) {
        load_split(Xf, sm, sm + ARR, row0, NN);
        load_arr(B1,         sm + 2 * ARR, 0, 128);
        load_arr(B1 + 16384, sm + 3 * ARR, 0, 128);
        __syncthreads();
    } else {
        // 4-stage pipelined loads: one commit group per K-quarter
        #pragma unroll
        for (int kq = 0; kq < 4; kq++) {
            cpa_q(base,               Ahi,        row0, NN,  kq);
            cpa_q(base + ARR * 2,     Alo,        row0, NN,  kq);
            cpa_q(base + 2 * ARR * 2, B1,         0,    128, kq);
            cpa_q(base + 3 * ARR * 2, B1 + 16384, 0,    128, kq);
            if (NM == 2) {
                cpa_q(base + 4 * ARR * 2, B2,         0, 128, kq);
                cpa_q(base + 5 * ARR * 2, B2 + 16384, 0, 128, kq);
            }
            asm volatile("cp.async.commit_group;" ::: "memory");
        }
    }

    int wm = (wid & 7) * 16;
    int wn = (wid >> 3) * 64;

    float acc[NM][8][4];
    #pragma unroll
    for (int m = 0; m < NM; m++)
        #pragma unroll
        for (int j = 0; j < 8; j++)
            #pragma unroll
            for (int q = 0; q < 4; q++) acc[m][j][q] = 0.f;

    int a_row = (lane & 7) + ((lane >> 3) & 1) * 8;
    int a_col = (lane >> 4) * 8;
    int b_row = (lane & 7) + ((lane >> 4) & 1) * 8;
    int b_col = ((lane >> 3) & 1) * 8;

    #pragma unroll
    for (int kq = 0; kq < 4; kq++) {
        if (!XF32) {
            if (kq == 0) asm volatile("cp.async.wait_group 3;" ::: "memory");
            else if (kq == 1) asm volatile("cp.async.wait_group 2;" ::: "memory");
            else if (kq == 2) asm volatile("cp.async.wait_group 1;" ::: "memory");
            else asm volatile("cp.async.wait_group 0;" ::: "memory");
            __syncthreads();
        }
        #pragma unroll
        for (int kk = 0; kk < 32; kk += 16) {
            int k0 = kq * 32 + kk;
            unsigned aH[4], aL[4];
            {
                unsigned off = (unsigned)(((wm + a_row) * LDA + k0 + a_col) * 2);
                ldsm4(aH, base + off);
                ldsm4(aL, base + ARR * 2 + off);
            }
            #pragma unroll
            for (int m = 0; m < NM; m++) {
                unsigned bH[8][2], bL[8][2];
                #pragma unroll
                for (int p = 0; p < 4; p++) {
                    unsigned off = (unsigned)(((wn + p * 16 + b_row) * LDA + k0 + b_col) * 2);
                    unsigned r[4];
                    ldsm4(r, base + (2 + 2 * m) * ARR * 2 + off);
                    bH[2*p][0] = r[0]; bH[2*p][1] = r[1]; bH[2*p+1][0] = r[2]; bH[2*p+1][1] = r[3];
                    ldsm4(r, base + (3 + 2 * m) * ARR * 2 + off);
                    bL[2*p][0] = r[0]; bL[2*p][1] = r[1]; bL[2*p+1][0] = r[2]; bL[2*p+1][1] = r[3];
                }
                #pragma unroll
                for (int j = 0; j < 8; j++) {
                    mma_bf16(acc[m][j], aH, bH[j]);
                    mma_bf16(acc[m][j], aH, bL[j]);
                    mma_bf16(acc[m][j], aL, bH[j]);
                }
            }
        }
    }

    int er = lane >> 2, ec = (lane & 3) * 2;
    #pragma unroll
    for (int m = 0; m < NM; m++) {
        float* out = m ? out2 : out1;
        int r_lo = row0 + wm + er;
        int r_hi = r_lo + 8;
        #pragma unroll
        for (int j = 0; j < 8; j++) {
            int col = wn + j * 8 + ec;
            if (r_lo < NN) *(float2*)(out + (size_t)r_lo * HH + col) = make_float2(acc[m][j][0], acc[m][j][1]);
            if (r_hi < NN) *(float2*)(out + (size_t)r_hi * HH + col) = make_float2(acc[m][j][2], acc[m][j][3]);
        }
    }
}

// ------- edge aggregation + self-loop + bias + BN + ReLU + outputs (fused) -------
// coef computed inline from dinv; mode bit0: write fp32 hout; bit1: write bf16 splits
__global__ __launch_bounds__(256) void agg_bn(
    const float* __restrict__ tmp, const float* __restrict__ res,
    const float* __restrict__ bias, const float* __restrict__ gam,
    const float* __restrict__ bet, int use_res, float* __restrict__ hout,
    __nv_bfloat16* __restrict__ hhi, __nv_bfloat16* __restrict__ hlo, int mode)
{
    int warp = (blockIdx.x * blockDim.x + threadIdx.x) >> 5;
    int lane = threadIdx.x & 31;
    if (warp >= NN) return;
    int c = lane * 4;
    float4 acc = use_res ? *(const float4*)(res + (size_t)warp * HH + c)
                         : make_float4(0.f, 0.f, 0.f, 0.f);
    float dv = d_dinv[warp];
    int e = warp * CAP;
    int end = e + min(d_cursor[warp], CAP);
    for (; e + 3 < end; e += 4) {
        int s0 = __ldg(&d_csr_src[e]),     s1 = __ldg(&d_csr_src[e + 1]);
        int s2 = __ldg(&d_csr_src[e + 2]), s3 = __ldg(&d_csr_src[e + 3]);
        float c0 = __ldg(&d_dinv[s0]) * dv, c1 = __ldg(&d_dinv[s1]) * dv;
        float c2 = __ldg(&d_dinv[s2]) * dv, c3 = __ldg(&d_dinv[s3]) * dv;
        float4 v0 = *(const float4*)(tmp + (size_t)s0 * HH + c);
        float4 v1 = *(const float4*)(tmp + (size_t)s1 * HH + c);
        float4 v2 = *(const float4*)(tmp + (size_t)s2 * HH + c);
        float4 v3 = *(const float4*)(tmp + (size_t)s3 * HH + c);
        acc.x += c0 * v0.x + c1 * v1.x + c2 * v2.x + c3 * v3.x;
        acc.y += c0 * v0.y + c1 * v1.y + c2 * v2.y + c3 * v3.y;
        acc.z += c0 * v0.z + c1 * v1.z + c2 * v2.z + c3 * v3.z;
        acc.w += c0 * v0.w + c1 * v1.w + c2 * v2.w + c3 * v3.w;
    }
    for (; e < end; e++) {
        int s0 = __ldg(&d_csr_src[e]);
        float c0 = __ldg(&d_dinv[s0]) * dv;
        float4 v0 = *(const float4*)(tmp + (size_t)s0 * HH + c);
        acc.x += c0 * v0.x; acc.y += c0 * v0.y;
        acc.z += c0 * v0.z; acc.w += c0 * v0.w;
    }
    float d2 = dv * dv;
    float4 t  = *(const float4*)(tmp  + (size_t)warp * HH + c);
    float4 bb = *(const float4*)(bias + c);
    float4 gg = *(const float4*)(gam  + c);
    float4 ee = *(const float4*)(bet  + c);
    float4 o;
    o.x = fmaxf((acc.x + t.x * d2 + bb.x) * BNINV * gg.x + ee.x, 0.f);
    o.y = fmaxf((acc.y + t.y * d2 + bb.y) * BNINV * gg.y + ee.y, 0.f);
    o.z = fmaxf((acc.z + t.z * d2 + bb.z) * BNINV * gg.z + ee.z, 0.f);
    o.w = fmaxf((acc.w + t.w * d2 + bb.w) * BNINV * gg.w + ee.w, 0.f);
    if (mode & 1) *(float4*)(hout + (size_t)warp * HH + c) = o;
    if (mode & 2) {
        __nv_bfloat16 hx = __float2bfloat16_rn(o.x), hy = __float2bfloat16_rn(o.y);
        __nv_bfloat16 hz = __float2bfloat16_rn(o.z), hw = __float2bfloat16_rn(o.w);
        __nv_bfloat162 p01; p01.x = hx; p01.y = hy;
        __nv_bfloat162 p23; p23.x = hz; p23.y = hw;
        *(__nv_bfloat162*)(hhi + (size_t)warp * HH + c)     = p01;
        *(__nv_bfloat162*)(hhi + (size_t)warp * HH + c + 2) = p23;
        __nv_bfloat162 l01, l23;
        l01.x = __float2bfloat16_rn(o.x - __bfloat162float(hx));
        l01.y = __float2bfloat16_rn(o.y - __bfloat162float(hy));
        l23.x = __float2bfloat16_rn(o.z - __bfloat162float(hz));
        l23.y = __float2bfloat16_rn(o.w - __bfloat162float(hw));
        *(__nv_bfloat162*)(hlo + (size_t)warp * HH + c)     = l01;
        *(__nv_bfloat162*)(hlo + (size_t)warp * HH + c + 2) = l23;
    }
}

// ---------------- pool: batch sorted -> chunked max-reduce, few atomics ----------------
__global__ void pool_kernel(const float* __restrict__ h, const int* __restrict__ batch) {
    __shared__ int sbatch[128];
    int b0 = blockIdx.x * 128, t = threadIdx.x;
    int n1 = min(NN, b0 + 128);
    sbatch[t] = (b0 + t < NN) ? batch[b0 + t] : -1;
    __syncthreads();
    int cur = sbatch[0];
    float m = 0.f;
    for (int n = b0; n < n1; n++) {
        int g = sbatch[n - b0];
        if (g != cur) {
            atomicMax(&d_pool[cur * HH + t], __float_as_int(m));
            m = 0.f; cur = g;
        }
        m = fmaxf(m, h[(size_t)n * HH + t]);
    }
    atomicMax(&d_pool[cur * HH + t], __float_as_int(m));
}

// ---------------- MLP head ----------------
__global__ void head_kernel(const float* __restrict__ mW1, const float* __restrict__ mb1,
                            const float* __restrict__ mW2, const float* __restrict__ mb2,
                            float* __restrict__ out) {
    int g = blockIdx.x, t = threadIdx.x;
    __shared__ float p[128], z[128];
    p[t] = __int_as_float(d_pool[g * HH + t]);
    __syncthreads();
    float s = mb1[t];
    #pragma unroll 8
    for (int k = 0; k < 128; k++) s += p[k] * mW1[k * HH + t];
    z[t] = fmaxf(s, 0.f);
    __syncthreads();
    if (t < CC) {
        float o = mb2[t];
        #pragma unroll 8
        for (int k = 0; k < 128; k++) o += z[k] * mW2[k * CC + t];
        out[g * CC + t] = o;
    }
}

// ---------------- launcher ----------------
static cudaStream_t g_s1 = 0;
static cudaEvent_t  g_evFork = 0, g_evJoin = 0;

extern "C" void kernel_launch(void* const* d_in, const int* in_sizes, int n_in,
                              void* d_out, int out_size) {
    const float* x     = (const float*)d_in[0];
    const int*   ei    = (const int*)d_in[1];
    const int*   batch = (const int*)d_in[2];
    const float* W0    = (const float*)d_in[3];
    const float* b0    = (const float*)d_in[4];
    const float* g0    = (const float*)d_in[5];
    const float* be0   = (const float*)d_in[6];
    const float* Wh    = (const float*)d_in[7];
    const float* bh    = (const float*)d_in[8];
    const float* gh    = (const float*)d_in[9];
    const float* beh   = (const float*)d_in[10];
    const float* Rh    = (const float*)d_in[11];
    const float* mW1   = (const float*)d_in[12];
    const float* mb1   = (const float*)d_in[13];
    const float* mW2   = (const float*)d_in[14];
    const float* mb2   = (const float*)d_in[15];
    float* out = (float*)d_out;

    const int* src = ei;
    const int* dst = ei + EE;

    float *tmp, *agg, *h;
    __nv_bfloat16 *ahi, *alo, *wt;
    cudaGetSymbolAddress((void**)&tmp, d_tmp);
    cudaGetSymbolAddress((void**)&agg, d_agg);
    cudaGetSymbolAddress((void**)&h,   d_h);
    cudaGetSymbolAddress((void**)&ahi, d_ahi);
    cudaGetSymbolAddress((void**)&alo, d_alo);
    cudaGetSymbolAddress((void**)&wt,  d_wt);

    const int SM1 = 4 * ARR * 2;   // 139264 B
    const int SM2 = 6 * ARR * 2;   // 208896 B
    cudaFuncSetAttribute(gemm_tpl<1, true>,  cudaFuncAttributeMaxDynamicSharedMemorySize, SM1);
    cudaFuncSetAttribute(gemm_tpl<2, false>, cudaFuncAttributeMaxDynamicSharedMemorySize, SM2);

    if (!g_s1) {
        cudaStreamCreateWithFlags(&g_s1, cudaStreamNonBlocking);
        cudaEventCreateWithFlags(&g_evFork, cudaEventDisableTiming);
        cudaEventCreateWithFlags(&g_evJoin, cudaEventDisableTiming);
    }

    const int GEMM_GRID = (NN + 127) / 128;   // 391
    const int AGG_GRID  = (NN * 32 + 255) / 256;

    // ---- fork: bucket-CSR branch on g_s1, weight/GEMM branch on origin ----
    cudaEventRecord(g_evFork, 0);
    cudaStreamWaitEvent(g_s1, g_evFork, 0);

    zero_kernel<<<(NN + 255) / 256, 256, 0, g_s1>>>();
    fill_kernel<<<(EE + 255) / 256, 256, 0, g_s1>>>(src, dst);
    dinv_kernel<<<(NN + 255) / 256, 256, 0, g_s1>>>();
    cudaEventRecord(g_evJoin, g_s1);

    convert_w<<<(7 * HH * HH + 255) / 256, 256>>>(W0, Wh, Rh);
    gemm_tpl<1, true><<<GEMM_GRID, GEMM_NT, SM1>>>(x,
        (const __nv_bfloat16*)0, (const __nv_bfloat16*)0, wt,
        (const __nv_bfloat16*)0, tmp, (float*)0);

    cudaStreamWaitEvent(0, g_evJoin, 0);

    // ---- layer 0 epilogue ----
    agg_bn<<<AGG_GRID, 256>>>(tmp, (const float*)0, b0, g0, be0, 0, h, ahi, alo, 2);

    // ---- residual layers ----
    for (int i = 0; i < 3; i++) {
        const __nv_bfloat16* bW = wt + (size_t)(1 + i) * 32768;
        const __nv_bfloat16* bR = wt + (size_t)(4 + i) * 32768;
        gemm_tpl<2, false><<<GEMM_GRID, GEMM_NT, SM2>>>((const float*)0, ahi, alo, bW, bR, tmp, agg);
        agg_bn<<<AGG_GRID, 256>>>(tmp, agg, bh + i * HH, gh + i * HH, beh + i * HH, 1,
                                  h, ahi, alo, (i < 2) ? 2 : 1);
    }

    // ---- pool + head ----
    pool_kernel<<<(NN + 127) / 128, 128>>>(h, batch);
    head_kernel<<<GG, 128>>>(mW1, mb1, mW2, mb2, out);
}

// round 16
// speedup vs baseline: 1.0151x; 1.0151x over previous
#include <cuda_runtime.h>
#include <cuda_bf16.h>

#define NN 50000
#define EE 800000
#define HH 128
#define GG 64
#define CC 10
#define CAP 64                      // bucket capacity per node (max degree ~40)
#define BNINV 0.9999950000374997f   // 1/sqrt(1+1e-5)

// ---------------- scratch (device globals; no allocations) ----------------
__device__ float d_tmp[NN * HH];          // h @ W  (fp32)
__device__ float d_agg[NN * HH];          // residual h @ R (fp32)
__device__ float d_h[NN * HH];            // final layer activations (for pool)
__device__ __nv_bfloat16 d_ahi[NN * HH];  // activation hi (bf16)
__device__ __nv_bfloat16 d_alo[NN * HH];  // activation lo (bf16)
__device__ float d_dinv[NN];
__device__ int   d_cursor[NN];            // degree counters / bucket cursors
__device__ int   d_csr_src[NN * CAP];     // bucketed incoming-edge sources
__device__ int   d_pool[GG * HH];
__device__ __nv_bfloat16 d_wt[7 * 2 * HH * HH];  // 7 mats, [hi|lo], transposed [n][k]

// ---------------- setup kernels ----------------
__global__ void zero_kernel() {
    int i = blockIdx.x * blockDim.x + threadIdx.x;
    if (i < NN) d_cursor[i] = 0;
    if (i < GG * HH) d_pool[i] = 0;
}
__global__ void fill_kernel(const int* __restrict__ src, const int* __restrict__ dst) {
    int e = blockIdx.x * blockDim.x + threadIdx.x;
    if (e < EE) {
        int s = src[e], d = dst[e];
        int pos = atomicAdd(&d_cursor[d], 1);
        if (pos < CAP) d_csr_src[d * CAP + pos] = s;
    }
}
__global__ void dinv_kernel() {
    int i = blockIdx.x * blockDim.x + threadIdx.x;
    if (i < NN) d_dinv[i] = rsqrtf((float)min(d_cursor[i], CAP) + 1.0f);
}
__global__ void convert_w(const float* __restrict__ W0, const float* __restrict__ Wh,
                          const float* __restrict__ Rh) {
    int idx = blockIdx.x * blockDim.x + threadIdx.x;
    if (idx >= 7 * HH * HH) return;
    int j = idx >> 14, r = idx & 16383;
    int k = r >> 7, n = r & 127;
    const float* src = (j == 0) ? W0 : (j < 4 ? Wh + (j - 1) * HH * HH : Rh + (j - 4) * HH * HH);
    float v = src[k * HH + n];
    __nv_bfloat16 hi = __float2bfloat16_rn(v);
    d_wt[j * 32768 + n * HH + k]         = hi;   // transposed [n][k]
    d_wt[j * 32768 + 16384 + n * HH + k] = __float2bfloat16_rn(v - __bfloat162float(hi));
}

// ---------------- MMA helpers (plain PTX, valid on base sm_103) ----------------
__device__ __forceinline__ void ldsm4(unsigned* r, unsigned addr) {
    asm volatile("ldmatrix.sync.aligned.m8n8.x4.shared.b16 {%0,%1,%2,%3}, [%4];"
        : "=r"(r[0]), "=r"(r[1]), "=r"(r[2]), "=r"(r[3]) : "r"(addr));
}
__device__ __forceinline__ void mma_bf16(float* c, const unsigned* a, const unsigned* b) {
    asm volatile("mma.sync.aligned.m16n8k16.row.col.f32.bf16.bf16.f32 "
        "{%0,%1,%2,%3}, {%4,%5,%6,%7}, {%8,%9}, {%0,%1,%2,%3};"
        : "+f"(c[0]), "+f"(c[1]), "+f"(c[2]), "+f"(c[3])
        : "r"(a[0]), "r"(a[1]), "r"(a[2]), "r"(a[3]), "r"(b[0]), "r"(b[1]));
}
__device__ __forceinline__ unsigned smem_u32(const void* p) {
    unsigned a;
    asm("{ .reg .u64 t; cvta.to.shared.u64 t, %1; cvt.u32.u64 %0, t; }" : "=r"(a) : "l"(p));
    return a;
}

// ---------------- bf16 split GEMM (512 threads, 16 warps, 8x2 warp grid) ----------------
#define LDA 136
#define ARR (128 * LDA)                 // halves per array
#define GEMM_NT 512

// cp.async one K-half (64 cols = 8 x 16B per row) of one array
__device__ __forceinline__ void cpa_half(unsigned sdst, const __nv_bfloat16* __restrict__ g,
                                         int row0, int valid, int kh) {
    #pragma unroll
    for (int i = threadIdx.x; i < 1024; i += GEMM_NT) {
        int row = i >> 3;
        int col = kh * 64 + ((i & 7) << 3);
        int gr = row0 + row;
        int sz = (gr < valid) ? 16 : 0;
        if (gr >= valid) gr = 0;   // keep address in-bounds (unused when sz=0)
        unsigned sa = sdst + (unsigned)((row * LDA + col) * 2);
        asm volatile("cp.async.cg.shared.global [%0], [%1], 16, %2;"
            :: "r"(sa), "l"(g + (size_t)gr * HH + col), "r"(sz) : "memory");
    }
}
__device__ __forceinline__ void load_split(const float* __restrict__ g,
                                           __nv_bfloat16* shi, __nv_bfloat16* slo,
                                           int row0, int valid) {
    #pragma unroll
    for (int i = threadIdx.x; i < 4096; i += GEMM_NT) {
        int row = i >> 5, col = (i & 31) << 2;
        float4 v = make_float4(0.f, 0.f, 0.f, 0.f);
        if (row0 + row < valid) v = *(const float4*)(g + (size_t)(row0 + row) * HH + col);
        __nv_bfloat16 hx = __float2bfloat16_rn(v.x), hy = __float2bfloat16_rn(v.y);
        __nv_bfloat16 hz = __float2bfloat16_rn(v.z), hw = __float2bfloat16_rn(v.w);
        __nv_bfloat162 h01; h01.x = hx; h01.y = hy;
        __nv_bfloat162 h23; h23.x = hz; h23.y = hw;
        *(__nv_bfloat162*)(shi + row * LDA + col)     = h01;
        *(__nv_bfloat162*)(shi + row * LDA + col + 2) = h23;
        __nv_bfloat162 l01, l23;
        l01.x = __float2bfloat16_rn(v.x - __bfloat162float(hx));
        l01.y = __float2bfloat16_rn(v.y - __bfloat162float(hy));
        l23.x = __float2bfloat16_rn(v.z - __bfloat162float(hz));
        l23.y = __float2bfloat16_rn(v.w - __bfloat162float(hw));
        *(__nv_bfloat162*)(slo + row * LDA + col)     = l01;
        *(__nv_bfloat162*)(slo + row * LDA + col + 2) = l23;
    }
}

template <int NM, bool XF32>
__global__ __launch_bounds__(GEMM_NT, 1) void gemm_tpl(
    const float* __restrict__ Xf,
    const __nv_bfloat16* __restrict__ Ahi, const __nv_bfloat16* __restrict__ Alo,
    const __nv_bfloat16* __restrict__ B1,  const __nv_bfloat16* __restrict__ B2,
    float* __restrict__ out1, float* __restrict__ out2)
{
    extern __shared__ __nv_bfloat16 sm[];
    unsigned base = smem_u32(sm);
    int tid = threadIdx.x, lane = tid & 31, wid = tid >> 5;
    int row0 = blockIdx.x * 128;

    if (XF32) {
        // B tiles via cp.async FIRST, then the long split-conversion hides their latency.
        #pragma unroll
        for (int kh = 0; kh < 2; kh++) {
            cpa_half(base + 2 * ARR * 2, B1,         0, 128, kh);
            cpa_half(base + 3 * ARR * 2, B1 + 16384, 0, 128, kh);
        }
        asm volatile("cp.async.commit_group;" ::: "memory");
        load_split(Xf, sm, sm + ARR, row0, NN);
        asm volatile("cp.async.wait_group 0;" ::: "memory");
        __syncthreads();
    } else {
        // 2-stage pipelined loads: K-half 0 = group 0, K-half 1 = group 1
        #pragma unroll
        for (int kh = 0; kh < 2; kh++) {
            cpa_half(base,               Ahi,        row0, NN,  kh);
            cpa_half(base + ARR * 2,     Alo,        row0, NN,  kh);
            cpa_half(base + 2 * ARR * 2, B1,         0,    128, kh);
            cpa_half(base + 3 * ARR * 2, B1 + 16384, 0,    128, kh);
            if (NM == 2) {
                cpa_half(base + 4 * ARR * 2, B2,         0, 128, kh);
                cpa_half(base + 5 * ARR * 2, B2 + 16384, 0, 128, kh);
            }
            asm volatile("cp.async.commit_group;" ::: "memory");
        }
        asm volatile("cp.async.wait_group 1;" ::: "memory");
        __syncthreads();
    }

    int wm = (wid & 7) * 16;
    int wn = (wid >> 3) * 64;

    float acc[NM][8][4];
    #pragma unroll
    for (int m = 0; m < NM; m++)
        #pragma unroll
        for (int j = 0; j < 8; j++)
            #pragma unroll
            for (int q = 0; q < 4; q++) acc[m][j][q] = 0.f;

    int a_row = (lane & 7) + ((lane >> 3) & 1) * 8;
    int a_col = (lane >> 4) * 8;
    int b_row = (lane & 7) + ((lane >> 4) & 1) * 8;
    int b_col = ((lane >> 3) & 1) * 8;

    #pragma unroll
    for (int kh = 0; kh < 2; kh++) {
        if (!XF32 && kh == 1) {
            asm volatile("cp.async.wait_group 0;" ::: "memory");
            __syncthreads();
        }
        #pragma unroll
        for (int kk = 0; kk < 64; kk += 16) {
            int k0 = kh * 64 + kk;
            unsigned aH[4], aL[4];
            {
                unsigned off = (unsigned)(((wm + a_row) * LDA + k0 + a_col) * 2);
                ldsm4(aH, base + off);
                ldsm4(aL, base + ARR * 2 + off);
            }
            #pragma unroll
            for (int m = 0; m < NM; m++) {
                unsigned bH[8][2], bL[8][2];
                #pragma unroll
                for (int p = 0; p < 4; p++) {
                    unsigned off = (unsigned)(((wn + p * 16 + b_row) * LDA + k0 + b_col) * 2);
                    unsigned r[4];
                    ldsm4(r, base + (2 + 2 * m) * ARR * 2 + off);
                    bH[2*p][0] = r[0]; bH[2*p][1] = r[1]; bH[2*p+1][0] = r[2]; bH[2*p+1][1] = r[3];
                    ldsm4(r, base + (3 + 2 * m) * ARR * 2 + off);
                    bL[2*p][0] = r[0]; bL[2*p][1] = r[1]; bL[2*p+1][0] = r[2]; bL[2*p+1][1] = r[3];
                }
                #pragma unroll
                for (int j = 0; j < 8; j++) {
                    mma_bf16(acc[m][j], aH, bH[j]);
                    mma_bf16(acc[m][j], aH, bL[j]);
                    mma_bf16(acc[m][j], aL, bH[j]);
                }
            }
        }
    }

    int er = lane >> 2, ec = (lane & 3) * 2;
    #pragma unroll
    for (int m = 0; m < NM; m++) {
        float* out = m ? out2 : out1;
        int r_lo = row0 + wm + er;
        int r_hi = r_lo + 8;
        #pragma unroll
        for (int j = 0; j < 8; j++) {
            int col = wn + j * 8 + ec;
            if (r_lo < NN) *(float2*)(out + (size_t)r_lo * HH + col) = make_float2(acc[m][j][0], acc[m][j][1]);
            if (r_hi < NN) *(float2*)(out + (size_t)r_hi * HH + col) = make_float2(acc[m][j][2], acc[m][j][3]);
        }
    }
}

// ------- edge aggregation + self-loop + bias + BN + ReLU + outputs (fused) -------
// coef computed inline from dinv; mode bit0: write fp32 hout; bit1: write bf16 splits
__global__ __launch_bounds__(256) void agg_bn(
    const float* __restrict__ tmp, const float* __restrict__ res,
    const float* __restrict__ bias, const float* __restrict__ gam,
    const float* __restrict__ bet, int use_res, float* __restrict__ hout,
    __nv_bfloat16* __restrict__ hhi, __nv_bfloat16* __restrict__ hlo, int mode)
{
    int warp = (blockIdx.x * blockDim.x + threadIdx.x) >> 5;
    int lane = threadIdx.x & 31;
    if (warp >= NN) return;
    int c = lane * 4;
    float4 acc = use_res ? *(const float4*)(res + (size_t)warp * HH + c)
                         : make_float4(0.f, 0.f, 0.f, 0.f);
    float dv = d_dinv[warp];
    int e = warp * CAP;
    int end = e + min(d_cursor[warp], CAP);
    for (; e + 3 < end; e += 4) {
        int s0 = __ldg(&d_csr_src[e]),     s1 = __ldg(&d_csr_src[e + 1]);
        int s2 = __ldg(&d_csr_src[e + 2]), s3 = __ldg(&d_csr_src[e + 3]);
        float c0 = __ldg(&d_dinv[s0]) * dv, c1 = __ldg(&d_dinv[s1]) * dv;
        float c2 = __ldg(&d_dinv[s2]) * dv, c3 = __ldg(&d_dinv[s3]) * dv;
        float4 v0 = *(const float4*)(tmp + (size_t)s0 * HH + c);
        float4 v1 = *(const float4*)(tmp + (size_t)s1 * HH + c);
        float4 v2 = *(const float4*)(tmp + (size_t)s2 * HH + c);
        float4 v3 = *(const float4*)(tmp + (size_t)s3 * HH + c);
        acc.x += c0 * v0.x + c1 * v1.x + c2 * v2.x + c3 * v3.x;
        acc.y += c0 * v0.y + c1 * v1.y + c2 * v2.y + c3 * v3.y;
        acc.z += c0 * v0.z + c1 * v1.z + c2 * v2.z + c3 * v3.z;
        acc.w += c0 * v0.w + c1 * v1.w + c2 * v2.w + c3 * v3.w;
    }
    for (; e < end; e++) {
        int s0 = __ldg(&d_csr_src[e]);
        float c0 = __ldg(&d_dinv[s0]) * dv;
        float4 v0 = *(const float4*)(tmp + (size_t)s0 * HH + c);
        acc.x += c0 * v0.x; acc.y += c0 * v0.y;
        acc.z += c0 * v0.z; acc.w += c0 * v0.w;
    }
    float d2 = dv * dv;
    float4 t  = *(const float4*)(tmp  + (size_t)warp * HH + c);
    float4 bb = *(const float4*)(bias + c);
    float4 gg = *(const float4*)(gam  + c);
    float4 ee = *(const float4*)(bet  + c);
    float4 o;
    o.x = fmaxf((acc.x + t.x * d2 + bb.x) * BNINV * gg.x + ee.x, 0.f);
    o.y = fmaxf((acc.y + t.y * d2 + bb.y) * BNINV * gg.y + ee.y, 0.f);
    o.z = fmaxf((acc.z + t.z * d2 + bb.z) * BNINV * gg.z + ee.z, 0.f);
    o.w = fmaxf((acc.w + t.w * d2 + bb.w) * BNINV * gg.w + ee.w, 0.f);
    if (mode & 1) *(float4*)(hout + (size_t)warp * HH + c) = o;
    if (mode & 2) {
        __nv_bfloat16 hx = __float2bfloat16_rn(o.x), hy = __float2bfloat16_rn(o.y);
        __nv_bfloat16 hz = __float2bfloat16_rn(o.z), hw = __float2bfloat16_rn(o.w);
        __nv_bfloat162 p01; p01.x = hx; p01.y = hy;
        __nv_bfloat162 p23; p23.x = hz; p23.y = hw;
        *(__nv_bfloat162*)(hhi + (size_t)warp * HH + c)     = p01;
        *(__nv_bfloat162*)(hhi + (size_t)warp * HH + c + 2) = p23;
        __nv_bfloat162 l01, l23;
        l01.x = __float2bfloat16_rn(o.x - __bfloat162float(hx));
        l01.y = __float2bfloat16_rn(o.y - __bfloat162float(hy));
        l23.x = __float2bfloat16_rn(o.z - __bfloat162float(hz));
        l23.y = __float2bfloat16_rn(o.w - __bfloat162float(hw));
        *(__nv_bfloat162*)(hlo + (size_t)warp * HH + c)     = l01;
        *(__nv_bfloat162*)(hlo + (size_t)warp * HH + c + 2) = l23;
    }
}

// ---------------- pool: batch sorted -> chunked max-reduce, few atomics ----------------
__global__ void pool_kernel(const float* __restrict__ h, const int* __restrict__ batch) {
    __shared__ int sbatch[128];
    int b0 = blockIdx.x * 128, t = threadIdx.x;
    int n1 = min(NN, b0 + 128);
    sbatch[t] = (b0 + t < NN) ? batch[b0 + t] : -1;
    __syncthreads();
    int cur = sbatch[0];
    float m = 0.f;
    for (int n = b0; n < n1; n++) {
        int g = sbatch[n - b0];
        if (g != cur) {
            atomicMax(&d_pool[cur * HH + t], __float_as_int(m));
            m = 0.f; cur = g;
        }
        m = fmaxf(m, h[(size_t)n * HH + t]);
    }
    atomicMax(&d_pool[cur * HH + t], __float_as_int(m));
}

// ---------------- MLP head ----------------
__global__ void head_kernel(const float* __restrict__ mW1, const float* __restrict__ mb1,
                            const float* __restrict__ mW2, const float* __restrict__ mb2,
                            float* __restrict__ out) {
    int g = blockIdx.x, t = threadIdx.x;
    __shared__ float p[128], z[128];
    p[t] = __int_as_float(d_pool[g * HH + t]);
    __syncthreads();
    float s = mb1[t];
    #pragma unroll 8
    for (int k = 0; k < 128; k++) s += p[k] * mW1[k * HH + t];
    z[t] = fmaxf(s, 0.f);
    __syncthreads();
    if (t < CC) {
        float o = mb2[t];
        #pragma unroll 8
        for (int k = 0; k < 128; k++) o += z[k] * mW2[k * CC + t];
        out[g * CC + t] = o;
    }
}

// ---------------- launcher ----------------
static cudaStream_t g_s1 = 0;
static cudaEvent_t  g_evFork = 0, g_evJoin = 0;

extern "C" void kernel_launch(void* const* d_in, const int* in_sizes, int n_in,
                              void* d_out, int out_size) {
    const float* x     = (const float*)d_in[0];
    const int*   ei    = (const int*)d_in[1];
    const int*   batch = (const int*)d_in[2];
    const float* W0    = (const float*)d_in[3];
    const float* b0    = (const float*)d_in[4];
    const float* g0    = (const float*)d_in[5];
    const float* be0   = (const float*)d_in[6];
    const float* Wh    = (const float*)d_in[7];
    const float* bh    = (const float*)d_in[8];
    const float* gh    = (const float*)d_in[9];
    const float* beh   = (const float*)d_in[10];
    const float* Rh    = (const float*)d_in[11];
    const float* mW1   = (const float*)d_in[12];
    const float* mb1   = (const float*)d_in[13];
    const float* mW2   = (const float*)d_in[14];
    const float* mb2   = (const float*)d_in[15];
    float* out = (float*)d_out;

    const int* src = ei;
    const int* dst = ei + EE;

    float *tmp, *agg, *h;
    __nv_bfloat16 *ahi, *alo, *wt;
    cudaGetSymbolAddress((void**)&tmp, d_tmp);
    cudaGetSymbolAddress((void**)&agg, d_agg);
    cudaGetSymbolAddress((void**)&h,   d_h);
    cudaGetSymbolAddress((void**)&ahi, d_ahi);
    cudaGetSymbolAddress((void**)&alo, d_alo);
    cudaGetSymbolAddress((void**)&wt,  d_wt);

    const int SM1 = 4 * ARR * 2;   // 139264 B
    const int SM2 = 6 * ARR * 2;   // 208896 B
    cudaFuncSetAttribute(gemm_tpl<1, true>,  cudaFuncAttributeMaxDynamicSharedMemorySize, SM1);
    cudaFuncSetAttribute(gemm_tpl<2, false>, cudaFuncAttributeMaxDynamicSharedMemorySize, SM2);

    if (!g_s1) {
        cudaStreamCreateWithFlags(&g_s1, cudaStreamNonBlocking);
        cudaEventCreateWithFlags(&g_evFork, cudaEventDisableTiming);
        cudaEventCreateWithFlags(&g_evJoin, cudaEventDisableTiming);
    }

    const int GEMM_GRID = (NN + 127) / 128;   // 391
    const int AGG_GRID  = (NN * 32 + 255) / 256;

    // ---- fork: bucket-CSR branch on g_s1, weight/GEMM branch on origin ----
    cudaEventRecord(g_evFork, 0);
    cudaStreamWaitEvent(g_s1, g_evFork, 0);

    zero_kernel<<<(NN + 255) / 256, 256, 0, g_s1>>>();
    fill_kernel<<<(EE + 255) / 256, 256, 0, g_s1>>>(src, dst);
    dinv_kernel<<<(NN + 255) / 256, 256, 0, g_s1>>>();
    cudaEventRecord(g_evJoin, g_s1);

    convert_w<<<(7 * HH * HH + 255) / 256, 256>>>(W0, Wh, Rh);
    gemm_tpl<1, true><<<GEMM_GRID, GEMM_NT, SM1>>>(x,
        (const __nv_bfloat16*)0, (const __nv_bfloat16*)0, wt,
        (const __nv_bfloat16*)0, tmp, (float*)0);

    cudaStreamWaitEvent(0, g_evJoin, 0);

    // ---- layer 0 epilogue ----
    agg_bn<<<AGG_GRID, 256>>>(tmp, (const float*)0, b0, g0, be0, 0, h, ahi, alo, 2);

    // ---- residual layers ----
    for (int i = 0; i < 3; i++) {
        const __nv_bfloat16* bW = wt + (size_t)(1 + i) * 32768;
        const __nv_bfloat16* bR = wt + (size_t)(4 + i) * 32768;
        gemm_tpl<2, false><<<GEMM_GRID, GEMM_NT, SM2>>>((const float*)0, ahi, alo, bW, bR, tmp, agg);
        agg_bn<<<AGG_GRID, 256>>>(tmp, agg, bh + i * HH, gh + i * HH, beh + i * HH, 1,
                                  h, ahi, alo, (i < 2) ? 2 : 1);
    }

    // ---- pool + head ----
    pool_kernel<<<(NN + 127) / 128, 128>>>(h, batch);
    head_kernel<<<GG, 128>>>(mW1, mb1, mW2, mb2, out);
}